// round 8
// baseline (speedup 1.0000x reference)
#include <cuda_runtime.h>
#include <math.h>
#include <stdint.h>

#define B_    256
#define T_    128
#define WD_   300
#define DD_   50
#define IN_DIM_ 400
#define IN_PAD  416
#define ROWSP   130
#define ATTN_ 700
#define NPADA 768
#define KC_   1216
#define KA_   416
#define NF_   512
#define NCLS_ 19
#define M_    (B_*T_)
#define FEAT_ (NF_ + 2*IN_DIM_)
#define KT_   16
#define LDA   20                  // smem row stride (words); conflict-free for ldmatrix
#define ATILE_W (128*LDA)         // 2560 words
#define BTILE_W (256*LDA)         // 5120 words
#define STG_W  (ATILE_W + BTILE_W)
#define NSTG  4
#define SMEM_BYTES (NSTG*STG_W*4) // 122880

// ---------------- scratch ----------------
__device__ float g_inpm[B_*ROWSP*IN_PAD];
__device__ float g_WtT[NF_*KC_];
__device__ float g_WaTp[2*NPADA*KA_];
__device__ float g_c[2][B_*ATTN_];
__device__ float g_spart[6*M_];          // plane = w*3 + chunk
__device__ float g_cnnmax[B_*NF_];

__device__ __forceinline__ uint32_t f2tf32(float x) {
    uint32_t u;
    asm("cvt.rna.tf32.f32 %0, %1;" : "=r"(u) : "f"(x));
    return u;
}
__device__ __forceinline__ float rtf32(float x) { return __uint_as_float(f2tf32(x)); }

__device__ __forceinline__ void cpa16(uint32_t dst, const void* src) {
    asm volatile("cp.async.cg.shared.global [%0], [%1], 16;\n" :: "r"(dst), "l"(src));
}
#define CP_COMMIT() asm volatile("cp.async.commit_group;\n")
#define CP_WAIT(n)  asm volatile("cp.async.wait_group %0;\n" :: "n"(n))

__device__ __forceinline__ void ldsm4(uint32_t* r, uint32_t a) {
    asm volatile("ldmatrix.sync.aligned.m8n8.x4.shared.b16 {%0,%1,%2,%3}, [%4];"
        : "=r"(r[0]), "=r"(r[1]), "=r"(r[2]), "=r"(r[3]) : "r"(a));
}
__device__ __forceinline__ void ldsm2(uint32_t* r, uint32_t a) {
    asm volatile("ldmatrix.sync.aligned.m8n8.x2.shared.b16 {%0,%1}, [%2];"
        : "=r"(r[0]), "=r"(r[1]) : "r"(a));
}

#define MMA_TF32(c, a, b) \
    asm volatile("mma.sync.aligned.m16n8k8.row.col.f32.tf32.tf32.f32 " \
        "{%0,%1,%2,%3},{%4,%5,%6,%7},{%8,%9},{%0,%1,%2,%3};" \
        : "+f"(c[0]), "+f"(c[1]), "+f"(c[2]), "+f"(c[3]) \
        : "r"(a[0]), "r"(a[1]), "r"(a[2]), "r"(a[3]), "r"(b[0]), "r"(b[1]))

// ---------------- weight prep ----------------
__global__ void k_prep(const float* __restrict__ conv_w,
                       const float* __restrict__ Wa1,
                       const float* __restrict__ Wa2) {
    int idx = blockIdx.x * blockDim.x + threadIdx.x;
    const int NWT = NF_*KC_;
    const int NWA = NPADA*KA_;
    if (idx < NWT) {
        int o = idx / KC_, k = idx % KC_;
        float v = 0.f;
        if (k < 1200) {
            int h = k / 400, i = k - h*400;
            v = rtf32(conv_w[o*1200 + i*3 + h]);
        }
        g_WtT[idx] = v;
    } else if (idx < NWT + 2*NWA) {
        int j = idx - NWT;
        int w = j / NWA;
        int r = j % NWA;
        int e = r / KA_, i = r % KA_;
        const float* Wa = w ? Wa2 : Wa1;
        float v = 0.f;
        if (e < ATTN_ && i < IN_DIM_) v = rtf32(Wa[e*ATTN_ + i]);
        g_WaTp[w*NWA + r] = v;
    }
}

// ---------------- gather ----------------
__global__ void k_gather(const int* __restrict__ words,
                         const int* __restrict__ d1i,
                         const int* __restrict__ d2i,
                         const float* __restrict__ wemb,
                         const float* __restrict__ d1e,
                         const float* __restrict__ d2e,
                         const float* __restrict__ mask) {
    int idx = blockIdx.x * blockDim.x + threadIdx.x;
    if (idx >= B_*ROWSP*IN_PAD) return;
    int i = idx % IN_PAD;
    int r = (idx / IN_PAD) % ROWSP;
    int b = idx / (IN_PAD*ROWSP);
    float v = 0.f;
    if (r >= 1 && r <= T_ && i < IN_DIM_) {
        int m = b*T_ + (r-1);
        float x;
        if (i < WD_)            x = wemb[words[m]*WD_ + i];
        else if (i < WD_+DD_)   x = d1e[d1i[m]*DD_ + (i - WD_)];
        else                    x = d2e[d2i[m]*DD_ + (i - WD_ - DD_)];
        v = rtf32(x) * mask[m];
    }
    g_inpm[idx] = v;
}

// ---------------- c[b,e]: coalesced warp-per-row ----------------
__global__ void k_argc(const int* __restrict__ arg1,
                       const int* __restrict__ arg2,
                       const float* __restrict__ wemb,
                       const float* __restrict__ Wa1,
                       const float* __restrict__ Wa2) {
    int b = blockIdx.x, w = blockIdx.y;
    const int* arg = w ? arg2 : arg1;
    const float* Wa = w ? Wa2 : Wa1;
    __shared__ float ae[WD_];
    int aidx = arg[b];
    for (int d = threadIdx.x; d < WD_; d += blockDim.x)
        ae[d] = wemb[aidx*WD_ + d];
    __syncthreads();
    int warp = threadIdx.x >> 5, lane = threadIdx.x & 31;
    for (int e = warp; e < ATTN_; e += 8) {
        const float* row = Wa + e*ATTN_ + IN_DIM_;
        float s = 0.f;
        for (int d = lane; d < WD_; d += 32) s += ae[d] * row[d];
        #pragma unroll
        for (int off = 16; off > 0; off >>= 1)
            s += __shfl_xor_sync(0xffffffffu, s, off);
        if (lane == 0) g_c[w][b*ATTN_ + e] = s;
    }
}

// ---------------- unified GEMM: 128x256 tile, 512 thr, 4-stage pipeline ----------------
__global__ __launch_bounds__(512, 1) void k_gemm(const float* __restrict__ wr1,
                                                 const float* __restrict__ wr2) {
    extern __shared__ float smem[];
    __shared__ float cs[256], wrs[256];
    uint32_t sb = (uint32_t)__cvta_generic_to_shared(smem);

    int bid = blockIdx.x;
    int tid = threadIdx.x;
    int lane = tid & 31, warp = tid >> 5;
    int warpM = warp & 1, warpN = warp >> 1;   // 2 x 8 warp grid
    int g = lane >> 2, t = lane & 3;

    float acc[4][4][4];
    #pragma unroll
    for (int mi = 0; mi < 4; ++mi)
        #pragma unroll
        for (int ni = 0; ni < 4; ++ni)
            #pragma unroll
            for (int c = 0; c < 4; ++c) acc[mi][ni][c] = 0.f;

    uint32_t abuf[NSTG], bbuf[NSTG];
    #pragma unroll
    for (int s = 0; s < NSTG; ++s) {
        abuf[s] = sb + (uint32_t)(s*STG_W)*4;
        bbuf[s] = abuf[s] + ATILE_W*4;
    }

    bool isconv = bid < 512;
    int b, n0, NT;
    const float* Bsrc;
    int BK;
    int w = 0, chunk = 0;
    if (isconv) {
        b  = bid >> 1;
        n0 = (bid & 1) * 256;
        NT = KC_/KT_;               // 76
        Bsrc = g_WtT;
        BK = KC_;
    } else {
        int id = bid - 512;         // 1536 = 256b * 6
        b = id / 6;
        int r = id % 6;
        w = r / 3;
        chunk = r % 3;
        n0 = chunk * 256;
        NT = KA_/KT_;               // 26
        Bsrc = &g_WaTp[w*NPADA*KA_];
        BK = KA_;
        const float* wr = w ? wr2 : wr1;
        const float* cb = &g_c[w][b*ATTN_];
        if (tid < 256) {
            int n = n0 + tid;
            cs[tid]  = (n < ATTN_) ? cb[n] : 0.f;
            wrs[tid] = (n < ATTN_) ? wr[n] : 0.f;
        }
    }

    // tile loader: A 128 rows x 16k (512 cpa16), B 256 rows x 16k (1024 cpa16)
    auto load_tile = [&](int kt, int s) {
        int k0 = kt * KT_;
        {   // A: one cpa16 per thread
            int row = tid >> 2, grp = tid & 3;
            int k = k0 + grp*4;
            const float* srcA;
            if (isconv) {
                int h, i;
                if (k < 1200) { h = k / 400; i = k - h*400; }
                else          { h = 0;       i = k - 800; }
                srcA = &g_inpm[(b*ROWSP + row + h)*IN_PAD + i];
            } else {
                srcA = &g_inpm[(b*ROWSP + row + 1)*IN_PAD + k];
            }
            cpa16(abuf[s] + (uint32_t)(row*LDA + grp*4)*4, srcA);
        }
        #pragma unroll
        for (int it = 0; it < 2; ++it) {   // B: two cpa16 per thread
            int u = tid + it*512;
            int row = u >> 2, grp = u & 3;
            int k = k0 + grp*4;
            cpa16(bbuf[s] + (uint32_t)(row*LDA + grp*4)*4,
                  &Bsrc[(n0 + row)*BK + k]);
        }
        CP_COMMIT();
    };

    load_tile(0, 0);
    load_tile(1, 1);
    load_tile(2, 2);

    for (int kt = 0; kt < NT; ++kt) {
        CP_WAIT(2);
        __syncthreads();
        if (kt + 3 < NT) load_tile(kt + 3, (kt + 3) & 3);
        else             CP_COMMIT();
        int s = kt & 3;
        #pragma unroll
        for (int ks = 0; ks < 2; ++ks) {
            int kb = ks * 8;
            uint32_t af[4][4], bf[4][2];
            #pragma unroll
            for (int mi = 0; mi < 4; ++mi) {
                int row = warpM*64 + mi*16 + (lane & 7) + ((lane >> 3) & 1)*8;
                ldsm4(af[mi], abuf[s] + (uint32_t)(row*LDA + kb + ((lane >> 4) << 2))*4);
            }
            #pragma unroll
            for (int ni = 0; ni < 4; ++ni) {
                int row = warpN*32 + ni*8 + (lane & 7);
                ldsm2(bf[ni], bbuf[s] + (uint32_t)(row*LDA + kb + (((lane >> 3) & 1) << 2))*4);
            }
            #pragma unroll
            for (int mi = 0; mi < 4; ++mi)
                #pragma unroll
                for (int ni = 0; ni < 4; ++ni)
                    MMA_TF32(acc[mi][ni], af[mi], bf[ni]);
        }
    }
    __syncthreads();    // protect smem reuse in epilogues

    if (isconv) {
        // fused time-max: local, cross-g shuffle, cross-warpM via smem
        float cm[4][2];
        #pragma unroll
        for (int ni = 0; ni < 4; ++ni) { cm[ni][0] = -1e30f; cm[ni][1] = -1e30f; }
        #pragma unroll
        for (int mi = 0; mi < 4; ++mi)
            #pragma unroll
            for (int ni = 0; ni < 4; ++ni) {
                cm[ni][0] = fmaxf(cm[ni][0], fmaxf(acc[mi][ni][0], acc[mi][ni][2]));
                cm[ni][1] = fmaxf(cm[ni][1], fmaxf(acc[mi][ni][1], acc[mi][ni][3]));
            }
        #pragma unroll
        for (int off = 4; off < 32; off <<= 1)
            #pragma unroll
            for (int ni = 0; ni < 4; ++ni) {
                cm[ni][0] = fmaxf(cm[ni][0], __shfl_xor_sync(0xffffffffu, cm[ni][0], off));
                cm[ni][1] = fmaxf(cm[ni][1], __shfl_xor_sync(0xffffffffu, cm[ni][1], off));
            }
        float* smax = smem;     // [2][256]
        if (g == 0) {
            #pragma unroll
            for (int ni = 0; ni < 4; ++ni) {
                int col = warpN*32 + ni*8 + 2*t;
                smax[warpM*256 + col]     = cm[ni][0];
                smax[warpM*256 + col + 1] = cm[ni][1];
            }
        }
        __syncthreads();
        if (tid < 256)
            g_cnnmax[b*NF_ + n0 + tid] = fmaxf(smax[tid], smax[256 + tid]);
    } else {
        // fused tanh + wr-dot: local, cross-t shuffle, cross-warpN via smem
        float rowacc[4][2];
        #pragma unroll
        for (int mi = 0; mi < 4; ++mi) {
            #pragma unroll
            for (int rr = 0; rr < 2; ++rr) {
                float rp = 0.f;
                #pragma unroll
                for (int ni = 0; ni < 4; ++ni)
                    #pragma unroll
                    for (int c = 0; c < 2; ++c) {
                        int col = warpN*32 + ni*8 + 2*t + c;
                        rp += wrs[col] * tanhf(acc[mi][ni][rr*2 + c] + cs[col]);
                    }
                rowacc[mi][rr] = rp;
            }
        }
        #pragma unroll
        for (int off = 1; off < 4; off <<= 1)
            #pragma unroll
            for (int mi = 0; mi < 4; ++mi)
                #pragma unroll
                for (int rr = 0; rr < 2; ++rr)
                    rowacc[mi][rr] += __shfl_xor_sync(0xffffffffu, rowacc[mi][rr], off);
        float* red = smem;      // [8][128]
        if (t == 0) {
            #pragma unroll
            for (int mi = 0; mi < 4; ++mi)
                #pragma unroll
                for (int rr = 0; rr < 2; ++rr) {
                    int row = warpM*64 + mi*16 + g + rr*8;
                    red[warpN*128 + row] = rowacc[mi][rr];
                }
        }
        __syncthreads();
        if (tid < 128) {
            float s = 0.f;
            #pragma unroll
            for (int j = 0; j < 8; ++j) s += red[j*128 + tid];
            g_spart[(w*3 + chunk)*M_ + b*T_ + tid] = s;
        }
    }
}

// ---------------- fused softmax + wsum + final dense + softmax ----------------
__global__ __launch_bounds__(512) void k_post(const float* __restrict__ mask,
                                              const float* __restrict__ conv_b,
                                              const float* __restrict__ dw,
                                              const float* __restrict__ db,
                                              float* __restrict__ out) {
    int b = blockIdx.x;
    int tid = threadIdx.x;
    __shared__ float aw[2][128];
    __shared__ float sh[2][128];
    __shared__ float feat[FEAT_];
    __shared__ float lg[NCLS_];
    int w = (tid >> 7) & 1, t = tid & 127;

    float s = 0.f, e = 0.f;
    if (tid < 256) {
        #pragma unroll
        for (int c = 0; c < 3; ++c) s += g_spart[(w*3 + c)*M_ + b*T_ + t];
        if (mask[b*T_ + t] == 0.f) s = -1e30f;
        sh[w][t] = s;
    }
    __syncthreads();
    for (int o = 64; o > 0; o >>= 1) {
        if (tid < 256 && t < o) sh[w][t] = fmaxf(sh[w][t], sh[w][t + o]);
        __syncthreads();
    }
    float mx = (tid < 256) ? sh[w][0] : 0.f;
    __syncthreads();
    if (tid < 256) { e = expf(s - mx); sh[w][t] = e; }
    __syncthreads();
    for (int o = 64; o > 0; o >>= 1) {
        if (tid < 256 && t < o) sh[w][t] += sh[w][t + o];
        __syncthreads();
    }
    if (tid < 256) aw[w][t] = e / sh[w][0];
    __syncthreads();

    for (int idx = tid; idx < 2*IN_DIM_; idx += 512) {
        int w2 = idx / IN_DIM_, d = idx % IN_DIM_;
        float s2 = 0.f;
        #pragma unroll 4
        for (int t2 = 0; t2 < T_; ++t2)
            s2 += aw[w2][t2] * g_inpm[(b*ROWSP + t2 + 1)*IN_PAD + d];
        feat[NF_ + idx] = s2;
    }
    feat[tid] = tanhf(g_cnnmax[b*NF_ + tid] + conv_b[tid]);
    __syncthreads();

    int warp = tid >> 5, lane = tid & 31;
    for (int c = warp; c < NCLS_; c += 16) {
        float s3 = 0.f;
        for (int i = lane; i < FEAT_; i += 32) s3 += feat[i] * dw[c*FEAT_ + i];
        #pragma unroll
        for (int off = 16; off > 0; off >>= 1)
            s3 += __shfl_xor_sync(0xffffffffu, s3, off);
        if (lane == 0) lg[c] = s3 + db[c];
    }
    __syncthreads();
    if (tid == 0) {
        float mx2 = lg[0];
        #pragma unroll
        for (int c = 1; c < NCLS_; ++c) mx2 = fmaxf(mx2, lg[c]);
        float sm = 0.f, ee[NCLS_];
        #pragma unroll
        for (int c = 0; c < NCLS_; ++c) { ee[c] = expf(lg[c] - mx2); sm += ee[c]; }
        #pragma unroll
        for (int c = 0; c < NCLS_; ++c) out[b*NCLS_ + c] = ee[c] / sm;
    }
}

// ---------------- launch ----------------
extern "C" void kernel_launch(void* const* d_in, const int* in_sizes, int n_in,
                              void* d_out, int out_size) {
    const int*   words  = (const int*)d_in[0];
    const float* mask   = (const float*)d_in[1];
    const int*   d1i    = (const int*)d_in[2];
    const int*   d2i    = (const int*)d_in[3];
    const int*   arg1   = (const int*)d_in[7];
    const int*   arg2   = (const int*)d_in[8];
    const float* wemb   = (const float*)d_in[9];
    const float* d1e    = (const float*)d_in[10];
    const float* d2e    = (const float*)d_in[11];
    const float* Wa1    = (const float*)d_in[12];
    const float* wr1    = (const float*)d_in[13];
    const float* Wa2    = (const float*)d_in[14];
    const float* wr2    = (const float*)d_in[15];
    const float* conv_w = (const float*)d_in[16];
    const float* conv_b = (const float*)d_in[17];
    const float* dw     = (const float*)d_in[18];
    const float* db     = (const float*)d_in[19];
    float* out = (float*)d_out;

    cudaFuncSetAttribute(k_gemm, cudaFuncAttributeMaxDynamicSharedMemorySize, SMEM_BYTES);

    const int NPREP = NF_*KC_ + 2*NPADA*KA_;
    k_prep<<<(NPREP + 255)/256, 256>>>(conv_w, Wa1, Wa2);
    k_gather<<<(B_*ROWSP*IN_PAD + 255)/256, 256>>>(words, d1i, d2i, wemb, d1e, d2e, mask);
    k_argc<<<dim3(B_, 2), 256>>>(arg1, arg2, wemb, Wa1, Wa2);
    k_gemm<<<2048, 512, SMEM_BYTES>>>(wr1, wr2);
    k_post<<<B_, 512>>>(mask, conv_b, dw, db, out);
}

// round 9
// speedup vs baseline: 1.7563x; 1.7563x over previous
#include <cuda_runtime.h>
#include <cuda_bf16.h>
#include <math.h>
#include <stdint.h>

#define B_    256
#define T_    128
#define WD_   300
#define DD_   50
#define IN_DIM_ 400
#define IN_PAD  416
#define ROWSP   130
#define ATTN_ 700
#define NPADA 768
#define KC_   1216
#define KA_   416
#define NF_   512
#define NCLS_ 19
#define M_    (B_*T_)
#define FEAT_ (NF_ + 2*IN_DIM_)
#define KT_   32                   // bf16 k-tile
#define LDAB  80                   // smem row stride in BYTES (proven conflict-free)
#define TILE_B (128*LDAB)          // 10240 bytes per tile
#define NSTG  4
#define SMEM_BYTES (NSTG*2*TILE_B) // 81920

// ---------------- scratch ----------------
__device__ float          g_inpm[B_*ROWSP*IN_PAD];   // fp32 masked padded (for k_post)
__device__ __nv_bfloat16  g_inpb[B_*ROWSP*IN_PAD];   // bf16 copy (GEMM A)
__device__ __nv_bfloat16  g_Wth[NF_*KC_];            // conv weights bf16 [o][k]
__device__ __nv_bfloat16  g_WaTh[2*NPADA*KA_];       // Wa^T bf16 padded [e][i]
__device__ float g_c[2][B_*ATTN_];
__device__ float g_spart[2*6*M_];
__device__ float g_cnnmax[B_*NF_];

__device__ __forceinline__ void cpa16(uint32_t dst, const void* src) {
    asm volatile("cp.async.cg.shared.global [%0], [%1], 16;\n" :: "r"(dst), "l"(src));
}
#define CP_COMMIT() asm volatile("cp.async.commit_group;\n")
#define CP_WAIT(n)  asm volatile("cp.async.wait_group %0;\n" :: "n"(n))

__device__ __forceinline__ void ldsm4(uint32_t* r, uint32_t a) {
    asm volatile("ldmatrix.sync.aligned.m8n8.x4.shared.b16 {%0,%1,%2,%3}, [%4];"
        : "=r"(r[0]), "=r"(r[1]), "=r"(r[2]), "=r"(r[3]) : "r"(a));
}
__device__ __forceinline__ void ldsm2(uint32_t* r, uint32_t a) {
    asm volatile("ldmatrix.sync.aligned.m8n8.x2.shared.b16 {%0,%1}, [%2];"
        : "=r"(r[0]), "=r"(r[1]) : "r"(a));
}

#define MMA_BF16(c, a, b) \
    asm volatile("mma.sync.aligned.m16n8k16.row.col.f32.bf16.bf16.f32 " \
        "{%0,%1,%2,%3},{%4,%5,%6,%7},{%8,%9},{%0,%1,%2,%3};" \
        : "+f"(c[0]), "+f"(c[1]), "+f"(c[2]), "+f"(c[3]) \
        : "r"(a[0]), "r"(a[1]), "r"(a[2]), "r"(a[3]), "r"(b[0]), "r"(b[1]))

// ---------------- weight prep (bf16) ----------------
__global__ void k_prep(const float* __restrict__ conv_w,
                       const float* __restrict__ Wa1,
                       const float* __restrict__ Wa2) {
    int idx = blockIdx.x * blockDim.x + threadIdx.x;
    const int NWT = NF_*KC_;
    const int NWA = NPADA*KA_;
    if (idx < NWT) {
        int o = idx / KC_, k = idx % KC_;
        float v = 0.f;
        if (k < 1200) {
            int h = k / 400, i = k - h*400;
            v = conv_w[o*1200 + i*3 + h];
        }
        g_Wth[idx] = __float2bfloat16_rn(v);
    } else if (idx < NWT + 2*NWA) {
        int j = idx - NWT;
        int w = j / NWA;
        int r = j % NWA;
        int e = r / KA_, i = r % KA_;
        const float* Wa = w ? Wa2 : Wa1;
        float v = 0.f;
        if (e < ATTN_ && i < IN_DIM_) v = Wa[e*ATTN_ + i];
        g_WaTh[w*NWA + r] = __float2bfloat16_rn(v);
    }
}

// ---------------- gather: fp32 + bf16 copies ----------------
__global__ void k_gather(const int* __restrict__ words,
                         const int* __restrict__ d1i,
                         const int* __restrict__ d2i,
                         const float* __restrict__ wemb,
                         const float* __restrict__ d1e,
                         const float* __restrict__ d2e,
                         const float* __restrict__ mask) {
    int idx = blockIdx.x * blockDim.x + threadIdx.x;
    if (idx >= B_*ROWSP*IN_PAD) return;
    int i = idx % IN_PAD;
    int r = (idx / IN_PAD) % ROWSP;
    int b = idx / (IN_PAD*ROWSP);
    float v = 0.f;
    if (r >= 1 && r <= T_ && i < IN_DIM_) {
        int m = b*T_ + (r-1);
        float x;
        if (i < WD_)            x = wemb[words[m]*WD_ + i];
        else if (i < WD_+DD_)   x = d1e[d1i[m]*DD_ + (i - WD_)];
        else                    x = d2e[d2i[m]*DD_ + (i - WD_ - DD_)];
        v = x * mask[m];
    }
    g_inpm[idx] = v;
    g_inpb[idx] = __float2bfloat16_rn(v);
}

// ---------------- c[b,e]: coalesced warp-per-row (fp32, exact path) ----------------
__global__ void k_argc(const int* __restrict__ arg1,
                       const int* __restrict__ arg2,
                       const float* __restrict__ wemb,
                       const float* __restrict__ Wa1,
                       const float* __restrict__ Wa2) {
    int b = blockIdx.x, w = blockIdx.y;
    const int* arg = w ? arg2 : arg1;
    const float* Wa = w ? Wa2 : Wa1;
    __shared__ float ae[WD_];
    int aidx = arg[b];
    for (int d = threadIdx.x; d < WD_; d += blockDim.x)
        ae[d] = wemb[aidx*WD_ + d];
    __syncthreads();
    int warp = threadIdx.x >> 5, lane = threadIdx.x & 31;
    for (int e = warp; e < ATTN_; e += 8) {
        const float* row = Wa + e*ATTN_ + IN_DIM_;
        float s = 0.f;
        for (int d = lane; d < WD_; d += 32) s += ae[d] * row[d];
        #pragma unroll
        for (int off = 16; off > 0; off >>= 1)
            s += __shfl_xor_sync(0xffffffffu, s, off);
        if (lane == 0) g_c[w][b*ATTN_ + e] = s;
    }
}

// ---------------- unified bf16 GEMM: 128x128 tile, 4-stage pipeline ----------------
__global__ __launch_bounds__(256, 2) void k_gemm(const float* __restrict__ wr1,
                                                 const float* __restrict__ wr2) {
    extern __shared__ float smem[];
    __shared__ float cs[128], wrs[128];
    uint32_t sb = (uint32_t)__cvta_generic_to_shared(smem);

    int bid = blockIdx.x;
    int tid = threadIdx.x;
    int lane = tid & 31, warp = tid >> 5;
    int warpM = warp & 1, warpN = warp >> 1;   // 2 x 4 warp grid
    int g = lane >> 2, t = lane & 3;

    float acc[4][4][4];
    #pragma unroll
    for (int mi = 0; mi < 4; ++mi)
        #pragma unroll
        for (int ni = 0; ni < 4; ++ni)
            #pragma unroll
            for (int c = 0; c < 4; ++c) acc[mi][ni][c] = 0.f;

    uint32_t abuf[NSTG], bbuf[NSTG];
    #pragma unroll
    for (int s = 0; s < NSTG; ++s) {
        abuf[s] = sb + (uint32_t)(2*s)*TILE_B;
        bbuf[s] = sb + (uint32_t)(2*s + 1)*TILE_B;
    }

    bool isconv = bid < 1024;
    int b, n0, NT;
    const __nv_bfloat16* Bsrc;
    int BK;
    int w = 0, chunk = 0;
    if (isconv) {
        n0 = (bid & 3) << 7;
        b  = bid >> 2;
        NT = KC_/KT_;               // 38
        Bsrc = g_Wth;
        BK = KC_;
    } else {
        int id = bid - 1024;        // 3072
        w = id & 1;
        chunk = (id >> 1) % 6;
        b = id / 12;
        n0 = chunk * 128;
        NT = KA_/KT_;               // 13
        Bsrc = &g_WaTh[w*NPADA*KA_];
        BK = KA_;
        const float* wr = w ? wr2 : wr1;
        const float* cb = &g_c[w][b*ATTN_];
        if (tid < 128) {
            int n = n0 + tid;
            cs[tid]  = (n < ATTN_) ? cb[n] : 0.f;
            wrs[tid] = (n < ATTN_) ? wr[n] : 0.f;
        }
    }

    // tile loader: A 128 rows x 32 bf16 (512 16B units), B same; 2+2 cpa16/thread
    auto load_tile = [&](int kt, int s) {
        int k0 = kt * KT_;
        #pragma unroll
        for (int it = 0; it < 2; ++it) {
            int u = tid + it*256;
            int row = u >> 2, grp = u & 3;        // 4 groups of 8 bf16 per row
            int k = k0 + grp*8;
            const __nv_bfloat16* srcA;
            if (isconv) {
                int h, i;
                if (k < 1200) { h = k / 400; i = k - h*400; }
                else          { h = 0;       i = k - 800; }
                srcA = &g_inpb[(b*ROWSP + row + h)*IN_PAD + i];
            } else {
                srcA = &g_inpb[(b*ROWSP + row + 1)*IN_PAD + k];
            }
            cpa16(abuf[s] + (uint32_t)(row*LDAB + grp*16), srcA);
            cpa16(bbuf[s] + (uint32_t)(row*LDAB + grp*16),
                  &Bsrc[(n0 + row)*BK + k]);
        }
        CP_COMMIT();
    };

    load_tile(0, 0);
    load_tile(1, 1);
    load_tile(2, 2);

    for (int kt = 0; kt < NT; ++kt) {
        CP_WAIT(2);
        __syncthreads();
        if (kt + 3 < NT) load_tile(kt + 3, (kt + 3) & 3);
        else             CP_COMMIT();
        int s = kt & 3;
        #pragma unroll
        for (int ks = 0; ks < 2; ++ks) {          // two K=16 steps per 32-k tile
            uint32_t af[4][4], bf[4][2];
            #pragma unroll
            for (int mi = 0; mi < 4; ++mi) {
                int row = warpM*64 + mi*16 + (lane & 15);
                ldsm4(af[mi], abuf[s] + (uint32_t)(row*LDAB + ks*32 + ((lane >> 4) << 4)));
            }
            #pragma unroll
            for (int ni = 0; ni < 4; ++ni) {
                int row = warpN*32 + ni*8 + (lane & 7);
                ldsm2(bf[ni], bbuf[s] + (uint32_t)(row*LDAB + ks*32 + (((lane >> 3) & 1) << 4)));
            }
            #pragma unroll
            for (int mi = 0; mi < 4; ++mi)
                #pragma unroll
                for (int ni = 0; ni < 4; ++ni)
                    MMA_BF16(acc[mi][ni], af[mi], bf[ni]);
        }
    }
    __syncthreads();    // protect smem reuse in epilogues

    if (isconv) {
        float cm[4][2];
        #pragma unroll
        for (int ni = 0; ni < 4; ++ni) { cm[ni][0] = -1e30f; cm[ni][1] = -1e30f; }
        #pragma unroll
        for (int mi = 0; mi < 4; ++mi)
            #pragma unroll
            for (int ni = 0; ni < 4; ++ni) {
                cm[ni][0] = fmaxf(cm[ni][0], fmaxf(acc[mi][ni][0], acc[mi][ni][2]));
                cm[ni][1] = fmaxf(cm[ni][1], fmaxf(acc[mi][ni][1], acc[mi][ni][3]));
            }
        #pragma unroll
        for (int off = 4; off < 32; off <<= 1)
            #pragma unroll
            for (int ni = 0; ni < 4; ++ni) {
                cm[ni][0] = fmaxf(cm[ni][0], __shfl_xor_sync(0xffffffffu, cm[ni][0], off));
                cm[ni][1] = fmaxf(cm[ni][1], __shfl_xor_sync(0xffffffffu, cm[ni][1], off));
            }
        float* smax = smem;     // [2][128]
        if (g == 0) {
            #pragma unroll
            for (int ni = 0; ni < 4; ++ni) {
                int col = warpN*32 + ni*8 + 2*t;
                smax[warpM*128 + col]     = cm[ni][0];
                smax[warpM*128 + col + 1] = cm[ni][1];
            }
        }
        __syncthreads();
        if (tid < 128)
            g_cnnmax[b*NF_ + n0 + tid] = fmaxf(smax[tid], smax[128 + tid]);
    } else {
        float rowacc[4][2];
        #pragma unroll
        for (int mi = 0; mi < 4; ++mi) {
            #pragma unroll
            for (int rr = 0; rr < 2; ++rr) {
                float rp = 0.f;
                #pragma unroll
                for (int ni = 0; ni < 4; ++ni)
                    #pragma unroll
                    for (int c = 0; c < 2; ++c) {
                        int col = warpN*32 + ni*8 + 2*t + c;
                        rp += wrs[col] * tanhf(acc[mi][ni][rr*2 + c] + cs[col]);
                    }
                rowacc[mi][rr] = rp;
            }
        }
        #pragma unroll
        for (int off = 1; off < 4; off <<= 1)
            #pragma unroll
            for (int mi = 0; mi < 4; ++mi)
                #pragma unroll
                for (int rr = 0; rr < 2; ++rr)
                    rowacc[mi][rr] += __shfl_xor_sync(0xffffffffu, rowacc[mi][rr], off);
        float* red = smem;      // [4][128]
        if (t == 0) {
            #pragma unroll
            for (int mi = 0; mi < 4; ++mi)
                #pragma unroll
                for (int rr = 0; rr < 2; ++rr) {
                    int row = warpM*64 + mi*16 + g + rr*8;
                    red[warpN*128 + row] = rowacc[mi][rr];
                }
        }
        __syncthreads();
        if (tid < 128) {
            float s = red[tid] + red[128 + tid] + red[256 + tid] + red[384 + tid];
            g_spart[(w*6 + chunk)*M_ + b*T_ + tid] = s;
        }
    }
}

// ---------------- fused softmax + wsum + final dense + softmax ----------------
__global__ __launch_bounds__(512) void k_post(const float* __restrict__ mask,
                                              const float* __restrict__ conv_b,
                                              const float* __restrict__ dw,
                                              const float* __restrict__ db,
                                              float* __restrict__ out) {
    int b = blockIdx.x;
    int tid = threadIdx.x;
    __shared__ float aw[2][128];
    __shared__ float sh[2][128];
    __shared__ float feat[FEAT_];
    __shared__ float lg[NCLS_];
    int w = (tid >> 7) & 1, t = tid & 127;

    float s = 0.f, e = 0.f;
    if (tid < 256) {
        #pragma unroll
        for (int c = 0; c < 6; ++c) s += g_spart[(w*6 + c)*M_ + b*T_ + t];
        if (mask[b*T_ + t] == 0.f) s = -1e30f;
        sh[w][t] = s;
    }
    __syncthreads();
    for (int o = 64; o > 0; o >>= 1) {
        if (tid < 256 && t < o) sh[w][t] = fmaxf(sh[w][t], sh[w][t + o]);
        __syncthreads();
    }
    float mx = (tid < 256) ? sh[w][0] : 0.f;
    __syncthreads();
    if (tid < 256) { e = expf(s - mx); sh[w][t] = e; }
    __syncthreads();
    for (int o = 64; o > 0; o >>= 1) {
        if (tid < 256 && t < o) sh[w][t] += sh[w][t + o];
        __syncthreads();
    }
    if (tid < 256) aw[w][t] = e / sh[w][0];
    __syncthreads();

    for (int idx = tid; idx < 2*IN_DIM_; idx += 512) {
        int w2 = idx / IN_DIM_, d = idx % IN_DIM_;
        float s2 = 0.f;
        #pragma unroll 4
        for (int t2 = 0; t2 < T_; ++t2)
            s2 += aw[w2][t2] * g_inpm[(b*ROWSP + t2 + 1)*IN_PAD + d];
        feat[NF_ + idx] = s2;
    }
    feat[tid] = tanhf(g_cnnmax[b*NF_ + tid] + conv_b[tid]);
    __syncthreads();

    int warp = tid >> 5, lane = tid & 31;
    for (int c = warp; c < NCLS_; c += 16) {
        float s3 = 0.f;
        for (int i = lane; i < FEAT_; i += 32) s3 += feat[i] * dw[c*FEAT_ + i];
        #pragma unroll
        for (int off = 16; off > 0; off >>= 1)
            s3 += __shfl_xor_sync(0xffffffffu, s3, off);
        if (lane == 0) lg[c] = s3 + db[c];
    }
    __syncthreads();
    if (tid == 0) {
        float mx2 = lg[0];
        #pragma unroll
        for (int c = 1; c < NCLS_; ++c) mx2 = fmaxf(mx2, lg[c]);
        float sm = 0.f, ee[NCLS_];
        #pragma unroll
        for (int c = 0; c < NCLS_; ++c) { ee[c] = expf(lg[c] - mx2); sm += ee[c]; }
        #pragma unroll
        for (int c = 0; c < NCLS_; ++c) out[b*NCLS_ + c] = ee[c] / sm;
    }
}

// ---------------- launch ----------------
extern "C" void kernel_launch(void* const* d_in, const int* in_sizes, int n_in,
                              void* d_out, int out_size) {
    const int*   words  = (const int*)d_in[0];
    const float* mask   = (const float*)d_in[1];
    const int*   d1i    = (const int*)d_in[2];
    const int*   d2i    = (const int*)d_in[3];
    const int*   arg1   = (const int*)d_in[7];
    const int*   arg2   = (const int*)d_in[8];
    const float* wemb   = (const float*)d_in[9];
    const float* d1e    = (const float*)d_in[10];
    const float* d2e    = (const float*)d_in[11];
    const float* Wa1    = (const float*)d_in[12];
    const float* wr1    = (const float*)d_in[13];
    const float* Wa2    = (const float*)d_in[14];
    const float* wr2    = (const float*)d_in[15];
    const float* conv_w = (const float*)d_in[16];
    const float* conv_b = (const float*)d_in[17];
    const float* dw     = (const float*)d_in[18];
    const float* db     = (const float*)d_in[19];
    float* out = (float*)d_out;

    cudaFuncSetAttribute(k_gemm, cudaFuncAttributeMaxDynamicSharedMemorySize, SMEM_BYTES);

    const int NPREP = NF_*KC_ + 2*NPADA*KA_;
    k_prep<<<(NPREP + 255)/256, 256>>>(conv_w, Wa1, Wa2);
    k_gather<<<(B_*ROWSP*IN_PAD + 255)/256, 256>>>(words, d1i, d2i, wemb, d1e, d2e, mask);
    k_argc<<<dim3(B_, 2), 256>>>(arg1, arg2, wemb, Wa1, Wa2);
    k_gemm<<<4096, 256, SMEM_BYTES>>>(wr1, wr2);
    k_post<<<B_, 512>>>(mask, conv_b, dw, db, out);
}

// round 10
// speedup vs baseline: 1.9903x; 1.1332x over previous
#include <cuda_runtime.h>
#include <cuda_bf16.h>
#include <math.h>
#include <stdint.h>

#define B_    256
#define T_    128
#define WD_   300
#define DD_   50
#define IN_DIM_ 400
#define IN_PAD  416
#define ROWSP   130
#define ATTN_ 700
#define NPADA 768
#define KC2   1248                 // conv K: 3 taps * 416 (tile-aligned)
#define KA_   416
#define NF_   512
#define NCLS_ 19
#define M_    (B_*T_)
#define FEAT_ (NF_ + 2*IN_DIM_)
#define KT_   32                   // bf16 k-tile
#define LDAB  80                   // smem row stride in BYTES (conflict-free)
#define TILE_B (128*LDAB)          // 10240 bytes per tile
#define NSTG  4
#define SMEM_BYTES (NSTG*2*TILE_B) // 81920

// ---------------- scratch ----------------
__device__ __nv_bfloat16  g_inpb[B_*ROWSP*IN_PAD];   // masked, padded, bf16
__device__ __nv_bfloat16  g_Wth[NF_*KC2];            // conv weights bf16 [o][h*416+i]
__device__ __nv_bfloat16  g_WaTh[2*NPADA*KA_];       // Wa^T bf16 padded [e][i]
__device__ float g_c[2][B_*ATTN_];
__device__ float g_spart[2*6*M_];
__device__ float g_cnnmax[B_*NF_];

__device__ __forceinline__ void cpa16(uint32_t dst, const void* src) {
    asm volatile("cp.async.cg.shared.global [%0], [%1], 16;\n" :: "r"(dst), "l"(src));
}
#define CP_COMMIT() asm volatile("cp.async.commit_group;\n")
#define CP_WAIT(n)  asm volatile("cp.async.wait_group %0;\n" :: "n"(n))

__device__ __forceinline__ void ldsm4(uint32_t* r, uint32_t a) {
    asm volatile("ldmatrix.sync.aligned.m8n8.x4.shared.b16 {%0,%1,%2,%3}, [%4];"
        : "=r"(r[0]), "=r"(r[1]), "=r"(r[2]), "=r"(r[3]) : "r"(a));
}

#define MMA_BF16(c, a, b) \
    asm volatile("mma.sync.aligned.m16n8k16.row.col.f32.bf16.bf16.f32 " \
        "{%0,%1,%2,%3},{%4,%5,%6,%7},{%8,%9},{%0,%1,%2,%3};" \
        : "+f"(c[0]), "+f"(c[1]), "+f"(c[2]), "+f"(c[3]) \
        : "r"(a[0]), "r"(a[1]), "r"(a[2]), "r"(a[3]), "r"(b[0]), "r"(b[1]))

// ---------------- weight prep (bf16) ----------------
__global__ void k_prep(const float* __restrict__ conv_w,
                       const float* __restrict__ Wa1,
                       const float* __restrict__ Wa2) {
    int idx = blockIdx.x * blockDim.x + threadIdx.x;
    const int NWT = NF_*KC2;
    const int NWA = NPADA*KA_;
    if (idx < NWT) {
        int o = idx / KC2, k = idx % KC2;
        int h = k / 416, i = k - h*416;
        float v = (i < 400) ? conv_w[o*1200 + i*3 + h] : 0.f;
        g_Wth[idx] = __float2bfloat16_rn(v);
    } else if (idx < NWT + 2*NWA) {
        int j = idx - NWT;
        int w = j / NWA;
        int r = j % NWA;
        int e = r / KA_, i = r % KA_;
        const float* Wa = w ? Wa2 : Wa1;
        float v = 0.f;
        if (e < ATTN_ && i < IN_DIM_) v = Wa[e*ATTN_ + i];
        g_WaTh[w*NWA + r] = __float2bfloat16_rn(v);
    }
}

// ---------------- gather: bf16, masked, padded ----------------
__global__ void k_gather(const int* __restrict__ words,
                         const int* __restrict__ d1i,
                         const int* __restrict__ d2i,
                         const float* __restrict__ wemb,
                         const float* __restrict__ d1e,
                         const float* __restrict__ d2e,
                         const float* __restrict__ mask) {
    int idx = blockIdx.x * blockDim.x + threadIdx.x;
    if (idx >= B_*ROWSP*IN_PAD) return;
    int i = idx % IN_PAD;
    int r = (idx / IN_PAD) % ROWSP;
    int b = idx / (IN_PAD*ROWSP);
    float v = 0.f;
    if (r >= 1 && r <= T_ && i < IN_DIM_) {
        int m = b*T_ + (r-1);
        float x;
        if (i < WD_)            x = wemb[words[m]*WD_ + i];
        else if (i < WD_+DD_)   x = d1e[d1i[m]*DD_ + (i - WD_)];
        else                    x = d2e[d2i[m]*DD_ + (i - WD_ - DD_)];
        v = x * mask[m];
    }
    g_inpb[idx] = __float2bfloat16_rn(v);
}

// ---------------- c[b,e]: coalesced warp-per-row (fp32) ----------------
__global__ void k_argc(const int* __restrict__ arg1,
                       const int* __restrict__ arg2,
                       const float* __restrict__ wemb,
                       const float* __restrict__ Wa1,
                       const float* __restrict__ Wa2) {
    int b = blockIdx.x, w = blockIdx.y;
    const int* arg = w ? arg2 : arg1;
    const float* Wa = w ? Wa2 : Wa1;
    __shared__ float ae[WD_];
    int aidx = arg[b];
    for (int d = threadIdx.x; d < WD_; d += blockDim.x)
        ae[d] = wemb[aidx*WD_ + d];
    __syncthreads();
    int warp = threadIdx.x >> 5, lane = threadIdx.x & 31;
    for (int e = warp; e < ATTN_; e += 8) {
        const float* row = Wa + e*ATTN_ + IN_DIM_;
        float s = 0.f;
        for (int d = lane; d < WD_; d += 32) s += ae[d] * row[d];
        #pragma unroll
        for (int off = 16; off > 0; off >>= 1)
            s += __shfl_xor_sync(0xffffffffu, s, off);
        if (lane == 0) g_c[w][b*ATTN_ + e] = s;
    }
}

// ---------------- unified bf16 GEMM: 128x128 tile, 4-stage pipeline ----------------
__global__ __launch_bounds__(256, 2) void k_gemm(const float* __restrict__ wr1,
                                                 const float* __restrict__ wr2) {
    extern __shared__ float smem[];
    __shared__ float cs[128], wrs[128];
    uint32_t sb = (uint32_t)__cvta_generic_to_shared(smem);

    int bid = blockIdx.x;
    int tid = threadIdx.x;
    int lane = tid & 31, warp = tid >> 5;
    int warpM = warp & 1, warpN = warp >> 1;   // 2 x 4 warp grid
    int g = lane >> 2, t = lane & 3;

    float acc[4][4][4];
    #pragma unroll
    for (int mi = 0; mi < 4; ++mi)
        #pragma unroll
        for (int ni = 0; ni < 4; ++ni)
            #pragma unroll
            for (int c = 0; c < 4; ++c) acc[mi][ni][c] = 0.f;

    uint32_t abuf[NSTG], bbuf[NSTG];
    #pragma unroll
    for (int s = 0; s < NSTG; ++s) {
        abuf[s] = sb + (uint32_t)(2*s)*TILE_B;
        bbuf[s] = sb + (uint32_t)(2*s + 1)*TILE_B;
    }

    bool isconv = bid < 1024;
    int b, n0, NT;
    const __nv_bfloat16* Bsrc;
    int BK;
    int w = 0, chunk = 0;
    if (isconv) {
        n0 = (bid & 3) << 7;
        b  = bid >> 2;
        NT = KC2/KT_;               // 39
        Bsrc = g_Wth;
        BK = KC2;
    } else {
        int id = bid - 1024;        // 3072
        w = id & 1;
        chunk = (id >> 1) % 6;
        b = id / 12;
        n0 = chunk * 128;
        NT = KA_/KT_;               // 13
        Bsrc = &g_WaTh[w*NPADA*KA_];
        BK = KA_;
        const float* wr = w ? wr2 : wr1;
        const float* cb = &g_c[w][b*ATTN_];
        if (tid < 128) {
            int n = n0 + tid;
            cs[tid]  = (n < ATTN_) ? cb[n] : 0.f;
            wrs[tid] = (n < ATTN_) ? wr[n] : 0.f;
        }
    }

    // per-thread loader coords (constant across tiles)
    int l_row = tid >> 2, l_grp = tid & 3;
    int l_row2 = (tid + 256) >> 2, l_grp2 = (tid + 256) & 3;

    // tile loader: per-tile tap/h computed ONCE (no per-element division)
    auto load_tile = [&](int ck, int s) {
        int k0 = ck * KT_;
        int h, i0;
        if (isconv) { h = ck / 13; i0 = (ck - h*13) * 32; }
        else        { h = 1;       i0 = k0; }
        cpa16(abuf[s] + (uint32_t)(l_row*LDAB + l_grp*16),
              &g_inpb[(b*ROWSP + l_row + h)*IN_PAD + i0 + l_grp*8]);
        cpa16(bbuf[s] + (uint32_t)(l_row*LDAB + l_grp*16),
              &Bsrc[(n0 + l_row)*BK + k0 + l_grp*8]);
        cpa16(abuf[s] + (uint32_t)(l_row2*LDAB + l_grp2*16),
              &g_inpb[(b*ROWSP + l_row2 + h)*IN_PAD + i0 + l_grp2*8]);
        cpa16(bbuf[s] + (uint32_t)(l_row2*LDAB + l_grp2*16),
              &Bsrc[(n0 + l_row2)*BK + k0 + l_grp2*8]);
        CP_COMMIT();
    };

    // precomputed fragment smem offsets
    uint32_t a_off[4], b_off[2];
    #pragma unroll
    for (int mi = 0; mi < 4; ++mi) {
        int row = warpM*64 + mi*16 + (lane & 15);
        a_off[mi] = (uint32_t)(row*LDAB + ((lane >> 4) << 4));
    }
    #pragma unroll
    for (int nip = 0; nip < 2; ++nip) {
        int row = warpN*32 + nip*16 + (lane & 7) + ((lane >> 4) << 3);
        b_off[nip] = (uint32_t)(row*LDAB + (((lane >> 3) & 1) << 4));
    }

    load_tile(0, 0);
    load_tile(1, 1);
    load_tile(2, 2);

    for (int kt = 0; kt < NT; ++kt) {
        CP_WAIT(2);
        __syncthreads();
        if (kt + 3 < NT) load_tile(kt + 3, (kt + 3) & 3);
        else             CP_COMMIT();
        int s = kt & 3;
        #pragma unroll
        for (int ks = 0; ks < 2; ++ks) {          // two K=16 steps per 32-k tile
            uint32_t af[4][4], bf[4][2];
            #pragma unroll
            for (int mi = 0; mi < 4; ++mi)
                ldsm4(af[mi], abuf[s] + a_off[mi] + ks*32);
            #pragma unroll
            for (int nip = 0; nip < 2; ++nip)
                ldsm4(&bf[2*nip][0], bbuf[s] + b_off[nip] + ks*32);
            #pragma unroll
            for (int mi = 0; mi < 4; ++mi)
                #pragma unroll
                for (int ni = 0; ni < 4; ++ni)
                    MMA_BF16(acc[mi][ni], af[mi], bf[ni]);
        }
    }
    __syncthreads();    // protect smem reuse in epilogues

    if (isconv) {
        float cm[4][2];
        #pragma unroll
        for (int ni = 0; ni < 4; ++ni) { cm[ni][0] = -1e30f; cm[ni][1] = -1e30f; }
        #pragma unroll
        for (int mi = 0; mi < 4; ++mi)
            #pragma unroll
            for (int ni = 0; ni < 4; ++ni) {
                cm[ni][0] = fmaxf(cm[ni][0], fmaxf(acc[mi][ni][0], acc[mi][ni][2]));
                cm[ni][1] = fmaxf(cm[ni][1], fmaxf(acc[mi][ni][1], acc[mi][ni][3]));
            }
        #pragma unroll
        for (int off = 4; off < 32; off <<= 1)
            #pragma unroll
            for (int ni = 0; ni < 4; ++ni) {
                cm[ni][0] = fmaxf(cm[ni][0], __shfl_xor_sync(0xffffffffu, cm[ni][0], off));
                cm[ni][1] = fmaxf(cm[ni][1], __shfl_xor_sync(0xffffffffu, cm[ni][1], off));
            }
        float* smax = smem;     // [2][128]
        if (g == 0) {
            #pragma unroll
            for (int ni = 0; ni < 4; ++ni) {
                int col = warpN*32 + ni*8 + 2*t;
                smax[warpM*128 + col]     = cm[ni][0];
                smax[warpM*128 + col + 1] = cm[ni][1];
            }
        }
        __syncthreads();
        if (tid < 128)
            g_cnnmax[b*NF_ + n0 + tid] = fmaxf(smax[tid], smax[128 + tid]);
    } else {
        float rowacc[4][2];
        #pragma unroll
        for (int mi = 0; mi < 4; ++mi) {
            #pragma unroll
            for (int rr = 0; rr < 2; ++rr) {
                float rp = 0.f;
                #pragma unroll
                for (int ni = 0; ni < 4; ++ni)
                    #pragma unroll
                    for (int c = 0; c < 2; ++c) {
                        int col = warpN*32 + ni*8 + 2*t + c;
                        rp += wrs[col] * tanhf(acc[mi][ni][rr*2 + c] + cs[col]);
                    }
                rowacc[mi][rr] = rp;
            }
        }
        #pragma unroll
        for (int off = 1; off < 4; off <<= 1)
            #pragma unroll
            for (int mi = 0; mi < 4; ++mi)
                #pragma unroll
                for (int rr = 0; rr < 2; ++rr)
                    rowacc[mi][rr] += __shfl_xor_sync(0xffffffffu, rowacc[mi][rr], off);
        float* red = smem;      // [4][128]
        if (t == 0) {
            #pragma unroll
            for (int mi = 0; mi < 4; ++mi)
                #pragma unroll
                for (int rr = 0; rr < 2; ++rr) {
                    int row = warpM*64 + mi*16 + g + rr*8;
                    red[warpN*128 + row] = rowacc[mi][rr];
                }
        }
        __syncthreads();
        if (tid < 128) {
            float s = red[tid] + red[128 + tid] + red[256 + tid] + red[384 + tid];
            g_spart[(w*6 + chunk)*M_ + b*T_ + tid] = s;
        }
    }
}

// ---------------- fused softmax + wsum + final dense + softmax ----------------
__global__ __launch_bounds__(512) void k_post(const float* __restrict__ mask,
                                              const float* __restrict__ conv_b,
                                              const float* __restrict__ dw,
                                              const float* __restrict__ db,
                                              float* __restrict__ out) {
    int b = blockIdx.x;
    int tid = threadIdx.x;
    __shared__ float aw[2][128];
    __shared__ float sh[2][128];
    __shared__ float feat[FEAT_];
    __shared__ float lg[NCLS_];
    int w = (tid >> 7) & 1, t = tid & 127;

    float s = 0.f, e = 0.f;
    if (tid < 256) {
        #pragma unroll
        for (int c = 0; c < 6; ++c) s += g_spart[(w*6 + c)*M_ + b*T_ + t];
        if (mask[b*T_ + t] == 0.f) s = -1e30f;
        sh[w][t] = s;
    }
    __syncthreads();
    for (int o = 64; o > 0; o >>= 1) {
        if (tid < 256 && t < o) sh[w][t] = fmaxf(sh[w][t], sh[w][t + o]);
        __syncthreads();
    }
    float mx = (tid < 256) ? sh[w][0] : 0.f;
    __syncthreads();
    if (tid < 256) { e = expf(s - mx); sh[w][t] = e; }
    __syncthreads();
    for (int o = 64; o > 0; o >>= 1) {
        if (tid < 256 && t < o) sh[w][t] += sh[w][t + o];
        __syncthreads();
    }
    if (tid < 256) aw[w][t] = e / sh[w][0];
    __syncthreads();

    for (int idx = tid; idx < 2*IN_DIM_; idx += 512) {
        int w2 = idx / IN_DIM_, d = idx % IN_DIM_;
        float s2 = 0.f;
        #pragma unroll 4
        for (int t2 = 0; t2 < T_; ++t2)
            s2 += aw[w2][t2] * __bfloat162float(g_inpb[(b*ROWSP + t2 + 1)*IN_PAD + d]);
        feat[NF_ + idx] = s2;
    }
    feat[tid] = tanhf(g_cnnmax[b*NF_ + tid] + conv_b[tid]);
    __syncthreads();

    int warp = tid >> 5, lane = tid & 31;
    for (int c = warp; c < NCLS_; c += 16) {
        float s3 = 0.f;
        for (int i = lane; i < FEAT_; i += 32) s3 += feat[i] * dw[c*FEAT_ + i];
        #pragma unroll
        for (int off = 16; off > 0; off >>= 1)
            s3 += __shfl_xor_sync(0xffffffffu, s3, off);
        if (lane == 0) lg[c] = s3 + db[c];
    }
    __syncthreads();
    if (tid == 0) {
        float mx2 = lg[0];
        #pragma unroll
        for (int c = 1; c < NCLS_; ++c) mx2 = fmaxf(mx2, lg[c]);
        float sm = 0.f, ee[NCLS_];
        #pragma unroll
        for (int c = 0; c < NCLS_; ++c) { ee[c] = expf(lg[c] - mx2); sm += ee[c]; }
        #pragma unroll
        for (int c = 0; c < NCLS_; ++c) out[b*NCLS_ + c] = ee[c] / sm;
    }
}

// ---------------- launch ----------------
extern "C" void kernel_launch(void* const* d_in, const int* in_sizes, int n_in,
                              void* d_out, int out_size) {
    const int*   words  = (const int*)d_in[0];
    const float* mask   = (const float*)d_in[1];
    const int*   d1i    = (const int*)d_in[2];
    const int*   d2i    = (const int*)d_in[3];
    const int*   arg1   = (const int*)d_in[7];
    const int*   arg2   = (const int*)d_in[8];
    const float* wemb   = (const float*)d_in[9];
    const float* d1e    = (const float*)d_in[10];
    const float* d2e    = (const float*)d_in[11];
    const float* Wa1    = (const float*)d_in[12];
    const float* wr1    = (const float*)d_in[13];
    const float* Wa2    = (const float*)d_in[14];
    const float* wr2    = (const float*)d_in[15];
    const float* conv_w = (const float*)d_in[16];
    const float* conv_b = (const float*)d_in[17];
    const float* dw     = (const float*)d_in[18];
    const float* db     = (const float*)d_in[19];
    float* out = (float*)d_out;

    cudaFuncSetAttribute(k_gemm, cudaFuncAttributeMaxDynamicSharedMemorySize, SMEM_BYTES);

    const int NPREP = NF_*KC2 + 2*NPADA*KA_;
    k_prep<<<(NPREP + 255)/256, 256>>>(conv_w, Wa1, Wa2);
    k_gather<<<(B_*ROWSP*IN_PAD + 255)/256, 256>>>(words, d1i, d2i, wemb, d1e, d2e, mask);
    k_argc<<<dim3(B_, 2), 256>>>(arg1, arg2, wemb, Wa1, Wa2);
    k_gemm<<<4096, 256, SMEM_BYTES>>>(wr1, wr2);
    k_post<<<B_, 512>>>(mask, conv_b, dw, db, out);
}

// round 11
// speedup vs baseline: 2.0068x; 1.0083x over previous
#include <cuda_runtime.h>
#include <cuda_bf16.h>
#include <math.h>
#include <stdint.h>

#define B_    256
#define T_    128
#define WD_   300
#define DD_   50
#define IN_DIM_ 400
#define IN_PAD  416
#define ROWSP   130
#define ATTN_ 700
#define NPADA 768
#define KC3   1280                 // conv K padded to 40 subchunks of 32
#define KA2   448                  // attn K padded to 14 subchunks of 32
#define NSC_C 40
#define NSC_A 14
#define NF_   512
#define NCLS_ 19
#define M_    (B_*T_)
#define FEAT_ (NF_ + 2*IN_DIM_)
#define LDAB  144                  // smem row stride BYTES (64-K stage; conflict-free)
#define TILE_B (128*LDAB)          // 18432 bytes per tile (A or B)
#define NSTG  3
#define SMEM_BYTES (NSTG*2*TILE_B) // 110592

// ---------------- scratch ----------------
__device__ __nv_bfloat16  g_inpb[B_*ROWSP*IN_PAD];   // masked, padded, bf16
__device__ __nv_bfloat16  g_Wth[NF_*KC3];            // conv weights bf16 [o][k], zero-padded
__device__ __nv_bfloat16  g_WaTh[2*NPADA*KA2];       // Wa^T bf16 padded [e][i], zero-padded
__device__ float g_c[2][B_*ATTN_];
__device__ float g_spart[2*6*M_];
__device__ float g_cnnmax[B_*NF_];

__device__ __forceinline__ void cpa16(uint32_t dst, const void* src) {
    asm volatile("cp.async.cg.shared.global [%0], [%1], 16;\n" :: "r"(dst), "l"(src));
}
#define CP_COMMIT() asm volatile("cp.async.commit_group;\n")
#define CP_WAIT(n)  asm volatile("cp.async.wait_group %0;\n" :: "n"(n))

__device__ __forceinline__ void ldsm4(uint32_t* r, uint32_t a) {
    asm volatile("ldmatrix.sync.aligned.m8n8.x4.shared.b16 {%0,%1,%2,%3}, [%4];"
        : "=r"(r[0]), "=r"(r[1]), "=r"(r[2]), "=r"(r[3]) : "r"(a));
}

#define MMA_BF16(c, a, b) \
    asm volatile("mma.sync.aligned.m16n8k16.row.col.f32.bf16.bf16.f32 " \
        "{%0,%1,%2,%3},{%4,%5,%6,%7},{%8,%9},{%0,%1,%2,%3};" \
        : "+f"(c[0]), "+f"(c[1]), "+f"(c[2]), "+f"(c[3]) \
        : "r"(a[0]), "r"(a[1]), "r"(a[2]), "r"(a[3]), "r"(b[0]), "r"(b[1]))

// ---------------- weight prep (bf16, zero-padded K) ----------------
__global__ void k_prep(const float* __restrict__ conv_w,
                       const float* __restrict__ Wa1,
                       const float* __restrict__ Wa2) {
    int idx = blockIdx.x * blockDim.x + threadIdx.x;
    const int NWT = NF_*KC3;
    const int NWA = NPADA*KA2;
    if (idx < NWT) {
        int o = idx / KC3, k = idx % KC3;
        float v = 0.f;
        if (k < 1248) {
            int h = k / 416, i = k - h*416;
            if (i < 400) v = conv_w[o*1200 + i*3 + h];
        }
        g_Wth[idx] = __float2bfloat16_rn(v);
    } else if (idx < NWT + 2*NWA) {
        int j = idx - NWT;
        int w = j / NWA;
        int r = j % NWA;
        int e = r / KA2, i = r % KA2;
        const float* Wa = w ? Wa2 : Wa1;
        float v = 0.f;
        if (e < ATTN_ && i < IN_DIM_) v = Wa[e*ATTN_ + i];
        g_WaTh[w*NWA + r] = __float2bfloat16_rn(v);
    }
}

// ---------------- gather: bf16, masked, padded ----------------
__global__ void k_gather(const int* __restrict__ words,
                         const int* __restrict__ d1i,
                         const int* __restrict__ d2i,
                         const float* __restrict__ wemb,
                         const float* __restrict__ d1e,
                         const float* __restrict__ d2e,
                         const float* __restrict__ mask) {
    int idx = blockIdx.x * blockDim.x + threadIdx.x;
    if (idx >= B_*ROWSP*IN_PAD) return;
    int i = idx % IN_PAD;
    int r = (idx / IN_PAD) % ROWSP;
    int b = idx / (IN_PAD*ROWSP);
    float v = 0.f;
    if (r >= 1 && r <= T_ && i < IN_DIM_) {
        int m = b*T_ + (r-1);
        float x;
        if (i < WD_)            x = wemb[words[m]*WD_ + i];
        else if (i < WD_+DD_)   x = d1e[d1i[m]*DD_ + (i - WD_)];
        else                    x = d2e[d2i[m]*DD_ + (i - WD_ - DD_)];
        v = x * mask[m];
    }
    g_inpb[idx] = __float2bfloat16_rn(v);
}

// ---------------- c[b,e]: coalesced warp-per-row (fp32) ----------------
__global__ void k_argc(const int* __restrict__ arg1,
                       const int* __restrict__ arg2,
                       const float* __restrict__ wemb,
                       const float* __restrict__ Wa1,
                       const float* __restrict__ Wa2) {
    int b = blockIdx.x, w = blockIdx.y;
    const int* arg = w ? arg2 : arg1;
    const float* Wa = w ? Wa2 : Wa1;
    __shared__ float ae[WD_];
    int aidx = arg[b];
    for (int d = threadIdx.x; d < WD_; d += blockDim.x)
        ae[d] = wemb[aidx*WD_ + d];
    __syncthreads();
    int warp = threadIdx.x >> 5, lane = threadIdx.x & 31;
    for (int e = warp; e < ATTN_; e += 8) {
        const float* row = Wa + e*ATTN_ + IN_DIM_;
        float s = 0.f;
        for (int d = lane; d < WD_; d += 32) s += ae[d] * row[d];
        #pragma unroll
        for (int off = 16; off > 0; off >>= 1)
            s += __shfl_xor_sync(0xffffffffu, s, off);
        if (lane == 0) g_c[w][b*ATTN_ + e] = s;
    }
}

// ---------------- unified bf16 GEMM: K=64 stages, 3-deep pipeline ----------------
__global__ __launch_bounds__(256, 2) void k_gemm(const float* __restrict__ wr1,
                                                 const float* __restrict__ wr2) {
    extern __shared__ float smem[];
    __shared__ float cs[128], wrs[128];
    uint32_t sb = (uint32_t)__cvta_generic_to_shared(smem);

    int bid = blockIdx.x;
    int tid = threadIdx.x;
    int lane = tid & 31, warp = tid >> 5;
    int warpM = warp & 1, warpN = warp >> 1;   // 2 x 4 warp grid
    int g = lane >> 2, t = lane & 3;

    float acc[4][4][4];
    #pragma unroll
    for (int mi = 0; mi < 4; ++mi)
        #pragma unroll
        for (int ni = 0; ni < 4; ++ni)
            #pragma unroll
            for (int c = 0; c < 4; ++c) acc[mi][ni][c] = 0.f;

    uint32_t abuf[NSTG], bbuf[NSTG];
    #pragma unroll
    for (int s = 0; s < NSTG; ++s) {
        abuf[s] = sb + (uint32_t)(2*s)*TILE_B;
        bbuf[s] = sb + (uint32_t)(2*s + 1)*TILE_B;
    }

    bool isconv = bid < 1024;
    int b, n0, NT, NSC;
    const __nv_bfloat16* Bsrc;
    int BK;
    int w = 0, chunk = 0;
    if (isconv) {
        n0 = (bid & 3) << 7;
        b  = bid >> 2;
        NT = NSC_C/2;               // 20 stages
        NSC = 39;                   // real subchunks
        Bsrc = g_Wth;
        BK = KC3;
    } else {
        int id = bid - 1024;        // 3072
        w = id & 1;
        chunk = (id >> 1) % 6;
        b = id / 12;
        n0 = chunk * 128;
        NT = NSC_A/2;               // 7 stages
        NSC = 13;
        Bsrc = &g_WaTh[w*NPADA*KA2];
        BK = KA2;
        const float* wr = w ? wr2 : wr1;
        const float* cb = &g_c[w][b*ATTN_];
        if (tid < 128) {
            int n = n0 + tid;
            cs[tid]  = (n < ATTN_) ? cb[n] : 0.f;
            wrs[tid] = (n < ATTN_) ? wr[n] : 0.f;
        }
    }

    // loader coords: 512 16B-units per 32-K subchunk, 2 per thread
    int l_row = tid >> 2, l_grp = tid & 3;
    int l_row2 = (tid + 256) >> 2, l_grp2 = (tid + 256) & 3;

    // load one stage = subchunks 2*st, 2*st+1 into column halves
    auto load_stage = [&](int st, int s) {
        #pragma unroll
        for (int sub = 0; sub < 2; ++sub) {
            int sc = 2*st + sub;
            int h, i0;
            if (isconv) {
                if (sc < 39) { h = sc / 13; i0 = (sc - h*13) * 32; }
                else         { h = 0; i0 = 0; }     // weights zero; any safe A addr
            } else {
                h = 1;
                i0 = (sc < 13) ? sc*32 : 0;         // weights zero for sc=13
            }
            int k0 = sc * 32;
            uint32_t colb = (uint32_t)(sub * 64);
            cpa16(abuf[s] + (uint32_t)(l_row*LDAB) + colb + (uint32_t)(l_grp*16),
                  &g_inpb[(b*ROWSP + l_row + h)*IN_PAD + i0 + l_grp*8]);
            cpa16(bbuf[s] + (uint32_t)(l_row*LDAB) + colb + (uint32_t)(l_grp*16),
                  &Bsrc[(n0 + l_row)*BK + k0 + l_grp*8]);
            cpa16(abuf[s] + (uint32_t)(l_row2*LDAB) + colb + (uint32_t)(l_grp2*16),
                  &g_inpb[(b*ROWSP + l_row2 + h)*IN_PAD + i0 + l_grp2*8]);
            cpa16(bbuf[s] + (uint32_t)(l_row2*LDAB) + colb + (uint32_t)(l_grp2*16),
                  &Bsrc[(n0 + l_row2)*BK + k0 + l_grp2*8]);
        }
        CP_COMMIT();
    };

    // precomputed fragment smem offsets
    uint32_t a_off[4], b_off[2];
    #pragma unroll
    for (int mi = 0; mi < 4; ++mi) {
        int row = warpM*64 + mi*16 + (lane & 15);
        a_off[mi] = (uint32_t)(row*LDAB + ((lane >> 4) << 4));
    }
    #pragma unroll
    for (int nip = 0; nip < 2; ++nip) {
        int row = warpN*32 + nip*16 + (lane & 7) + ((lane >> 4) << 3);
        b_off[nip] = (uint32_t)(row*LDAB + (((lane >> 3) & 1) << 4));
    }

    load_stage(0, 0);
    load_stage(1, 1);

    int s = 0;                       // rotating stage index
    for (int st = 0; st < NT; ++st) {
        CP_WAIT(1);
        __syncthreads();
        if (st + 2 < NT) {
            int s2 = s + 2; if (s2 >= NSTG) s2 -= NSTG;
            load_stage(st + 2, s2);
        } else {
            CP_COMMIT();
        }
        #pragma unroll
        for (int ks = 0; ks < 4; ++ks) {       // four K=16 steps per 64-K stage
            uint32_t af[4][4], bf[4][2];
            #pragma unroll
            for (int mi = 0; mi < 4; ++mi)
                ldsm4(af[mi], abuf[s] + a_off[mi] + ks*32);
            #pragma unroll
            for (int nip = 0; nip < 2; ++nip)
                ldsm4(&bf[2*nip][0], bbuf[s] + b_off[nip] + ks*32);
            #pragma unroll
            for (int mi = 0; mi < 4; ++mi)
                #pragma unroll
                for (int ni = 0; ni < 4; ++ni)
                    MMA_BF16(acc[mi][ni], af[mi], bf[ni]);
        }
        if (++s >= NSTG) s = 0;
    }
    __syncthreads();    // protect smem reuse in epilogues

    if (isconv) {
        float cm[4][2];
        #pragma unroll
        for (int ni = 0; ni < 4; ++ni) { cm[ni][0] = -1e30f; cm[ni][1] = -1e30f; }
        #pragma unroll
        for (int mi = 0; mi < 4; ++mi)
            #pragma unroll
            for (int ni = 0; ni < 4; ++ni) {
                cm[ni][0] = fmaxf(cm[ni][0], fmaxf(acc[mi][ni][0], acc[mi][ni][2]));
                cm[ni][1] = fmaxf(cm[ni][1], fmaxf(acc[mi][ni][1], acc[mi][ni][3]));
            }
        #pragma unroll
        for (int off = 4; off < 32; off <<= 1)
            #pragma unroll
            for (int ni = 0; ni < 4; ++ni) {
                cm[ni][0] = fmaxf(cm[ni][0], __shfl_xor_sync(0xffffffffu, cm[ni][0], off));
                cm[ni][1] = fmaxf(cm[ni][1], __shfl_xor_sync(0xffffffffu, cm[ni][1], off));
            }
        float* smax = smem;     // [2][128]
        if (g == 0) {
            #pragma unroll
            for (int ni = 0; ni < 4; ++ni) {
                int col = warpN*32 + ni*8 + 2*t;
                smax[warpM*128 + col]     = cm[ni][0];
                smax[warpM*128 + col + 1] = cm[ni][1];
            }
        }
        __syncthreads();
        if (tid < 128)
            g_cnnmax[b*NF_ + n0 + tid] = fmaxf(smax[tid], smax[128 + tid]);
    } else {
        float rowacc[4][2];
        #pragma unroll
        for (int mi = 0; mi < 4; ++mi) {
            #pragma unroll
            for (int rr = 0; rr < 2; ++rr) {
                float rp = 0.f;
                #pragma unroll
                for (int ni = 0; ni < 4; ++ni)
                    #pragma unroll
                    for (int c = 0; c < 2; ++c) {
                        int col = warpN*32 + ni*8 + 2*t + c;
                        rp += wrs[col] * tanhf(acc[mi][ni][rr*2 + c] + cs[col]);
                    }
                rowacc[mi][rr] = rp;
            }
        }
        #pragma unroll
        for (int off = 1; off < 4; off <<= 1)
            #pragma unroll
            for (int mi = 0; mi < 4; ++mi)
                #pragma unroll
                for (int rr = 0; rr < 2; ++rr)
                    rowacc[mi][rr] += __shfl_xor_sync(0xffffffffu, rowacc[mi][rr], off);
        float* red = smem;      // [4][128]
        if (t == 0) {
            #pragma unroll
            for (int mi = 0; mi < 4; ++mi)
                #pragma unroll
                for (int rr = 0; rr < 2; ++rr) {
                    int row = warpM*64 + mi*16 + g + rr*8;
                    red[warpN*128 + row] = rowacc[mi][rr];
                }
        }
        __syncthreads();
        if (tid < 128) {
            float sv = red[tid] + red[128 + tid] + red[256 + tid] + red[384 + tid];
            g_spart[(w*6 + chunk)*M_ + b*T_ + tid] = sv;
        }
    }
}

// ---------------- fused softmax + wsum + final dense + softmax ----------------
__global__ __launch_bounds__(512) void k_post(const float* __restrict__ mask,
                                              const float* __restrict__ conv_b,
                                              const float* __restrict__ dw,
                                              const float* __restrict__ db,
                                              float* __restrict__ out) {
    int b = blockIdx.x;
    int tid = threadIdx.x;
    __shared__ float aw[2][128];
    __shared__ float sh[2][128];
    __shared__ float feat[FEAT_];
    __shared__ float lg[NCLS_];
    int w = (tid >> 7) & 1, t = tid & 127;

    float s = 0.f, e = 0.f;
    if (tid < 256) {
        #pragma unroll
        for (int c = 0; c < 6; ++c) s += g_spart[(w*6 + c)*M_ + b*T_ + t];
        if (mask[b*T_ + t] == 0.f) s = -1e30f;
        sh[w][t] = s;
    }
    __syncthreads();
    for (int o = 64; o > 0; o >>= 1) {
        if (tid < 256 && t < o) sh[w][t] = fmaxf(sh[w][t], sh[w][t + o]);
        __syncthreads();
    }
    float mx = (tid < 256) ? sh[w][0] : 0.f;
    __syncthreads();
    if (tid < 256) { e = expf(s - mx); sh[w][t] = e; }
    __syncthreads();
    for (int o = 64; o > 0; o >>= 1) {
        if (tid < 256 && t < o) sh[w][t] += sh[w][t + o];
        __syncthreads();
    }
    if (tid < 256) aw[w][t] = e / sh[w][0];
    __syncthreads();

    for (int idx = tid; idx < 2*IN_DIM_; idx += 512) {
        int w2 = idx / IN_DIM_, d = idx % IN_DIM_;
        float s2 = 0.f;
        #pragma unroll 4
        for (int t2 = 0; t2 < T_; ++t2)
            s2 += aw[w2][t2] * __bfloat162float(g_inpb[(b*ROWSP + t2 + 1)*IN_PAD + d]);
        feat[NF_ + idx] = s2;
    }
    feat[tid] = tanhf(g_cnnmax[b*NF_ + tid] + conv_b[tid]);
    __syncthreads();

    int warp = tid >> 5, lane = tid & 31;
    for (int c = warp; c < NCLS_; c += 16) {
        float s3 = 0.f;
        for (int i = lane; i < FEAT_; i += 32) s3 += feat[i] * dw[c*FEAT_ + i];
        #pragma unroll
        for (int off = 16; off > 0; off >>= 1)
            s3 += __shfl_xor_sync(0xffffffffu, s3, off);
        if (lane == 0) lg[c] = s3 + db[c];
    }
    __syncthreads();
    if (tid == 0) {
        float mx2 = lg[0];
        #pragma unroll
        for (int c = 1; c < NCLS_; ++c) mx2 = fmaxf(mx2, lg[c]);
        float sm = 0.f, ee[NCLS_];
        #pragma unroll
        for (int c = 0; c < NCLS_; ++c) { ee[c] = expf(lg[c] - mx2); sm += ee[c]; }
        #pragma unroll
        for (int c = 0; c < NCLS_; ++c) out[b*NCLS_ + c] = ee[c] / sm;
    }
}

// ---------------- launch ----------------
extern "C" void kernel_launch(void* const* d_in, const int* in_sizes, int n_in,
                              void* d_out, int out_size) {
    const int*   words  = (const int*)d_in[0];
    const float* mask   = (const float*)d_in[1];
    const int*   d1i    = (const int*)d_in[2];
    const int*   d2i    = (const int*)d_in[3];
    const int*   arg1   = (const int*)d_in[7];
    const int*   arg2   = (const int*)d_in[8];
    const float* wemb   = (const float*)d_in[9];
    const float* d1e    = (const float*)d_in[10];
    const float* d2e    = (const float*)d_in[11];
    const float* Wa1    = (const float*)d_in[12];
    const float* wr1    = (const float*)d_in[13];
    const float* Wa2    = (const float*)d_in[14];
    const float* wr2    = (const float*)d_in[15];
    const float* conv_w = (const float*)d_in[16];
    const float* conv_b = (const float*)d_in[17];
    const float* dw     = (const float*)d_in[18];
    const float* db     = (const float*)d_in[19];
    float* out = (float*)d_out;

    cudaFuncSetAttribute(k_gemm, cudaFuncAttributeMaxDynamicSharedMemorySize, SMEM_BYTES);

    const int NPREP = NF_*KC3 + 2*NPADA*KA2;
    k_prep<<<(NPREP + 255)/256, 256>>>(conv_w, Wa1, Wa2);
    k_gather<<<(B_*ROWSP*IN_PAD + 255)/256, 256>>>(words, d1i, d2i, wemb, d1e, d2e, mask);
    k_argc<<<dim3(B_, 2), 256>>>(arg1, arg2, wemb, Wa1, Wa2);
    k_gemm<<<4096, 256, SMEM_BYTES>>>(wr1, wr2);
    k_post<<<B_, 512>>>(mask, conv_b, dw, db, out);
}

// round 12
// speedup vs baseline: 2.1842x; 1.0884x over previous
#include <cuda_runtime.h>
#include <cuda_bf16.h>
#include <math.h>
#include <stdint.h>

#define B_    256
#define T_    128
#define WD_   300
#define DD_   50
#define IN_DIM_ 400
#define IN_PAD  416
#define ROWSP   130
#define ATTN_ 700
#define NPADA 768
#define KC3   1280                 // conv K padded (40 subchunks of 32)
#define KA2   448                  // attn K padded (14 subchunks)
#define KE_   320                  // arg-embed K padded (10 subchunks)
#define NSC_C 40
#define NSC_A 14
#define NF_   512
#define NCLS_ 19
#define M_    (B_*T_)
#define FEAT_ (NF_ + 2*IN_DIM_)
#define LDAB  144                  // smem row stride BYTES (conflict-free)
#define TILE_B (128*LDAB)
#define NSTG  3
#define SMEM_BYTES (NSTG*2*TILE_B) // 110592

// ---------------- scratch ----------------
__device__ __nv_bfloat16  g_inpb[B_*ROWSP*IN_PAD];
__device__ __nv_bfloat16  g_Wth[NF_*KC3];
__device__ __nv_bfloat16  g_WaTh[2*NPADA*KA2];
__device__ __nv_bfloat16  g_Wa2h[2*NPADA*KE_];       // Wa[:,400:700]^... [w][e][i], padded
__device__ __nv_bfloat16  g_argb[2*B_*KE_];          // arg embeddings [w][b][i], padded
__device__ float g_c[2][B_*ATTN_];
__device__ float g_spart[2*6*M_];
__device__ float g_cnnmax[B_*NF_];

__device__ __forceinline__ void cpa16(uint32_t dst, const void* src) {
    asm volatile("cp.async.cg.shared.global [%0], [%1], 16;\n" :: "r"(dst), "l"(src));
}
#define CP_COMMIT() asm volatile("cp.async.commit_group;\n")
#define CP_WAIT(n)  asm volatile("cp.async.wait_group %0;\n" :: "n"(n))

__device__ __forceinline__ void ldsm4(uint32_t* r, uint32_t a) {
    asm volatile("ldmatrix.sync.aligned.m8n8.x4.shared.b16 {%0,%1,%2,%3}, [%4];"
        : "=r"(r[0]), "=r"(r[1]), "=r"(r[2]), "=r"(r[3]) : "r"(a));
}

#define MMA_BF16(c, a, b) \
    asm volatile("mma.sync.aligned.m16n8k16.row.col.f32.bf16.bf16.f32 " \
        "{%0,%1,%2,%3},{%4,%5,%6,%7},{%8,%9},{%0,%1,%2,%3};" \
        : "+f"(c[0]), "+f"(c[1]), "+f"(c[2]), "+f"(c[3]) \
        : "r"(a[0]), "r"(a[1]), "r"(a[2]), "r"(a[3]), "r"(b[0]), "r"(b[1]))

// ---------------- weight prep (bf16, zero-padded K) ----------------
__global__ void k_prep(const float* __restrict__ conv_w,
                       const float* __restrict__ Wa1,
                       const float* __restrict__ Wa2) {
    int idx = blockIdx.x * blockDim.x + threadIdx.x;
    const int NWT = NF_*KC3;
    const int NWA = NPADA*KA2;
    const int NW2 = NPADA*KE_;
    if (idx < NWT) {
        int o = idx / KC3, k = idx % KC3;
        float v = 0.f;
        if (k < 1248) {
            int h = k / 416, i = k - h*416;
            if (i < 400) v = conv_w[o*1200 + i*3 + h];
        }
        g_Wth[idx] = __float2bfloat16_rn(v);
    } else if (idx < NWT + 2*NWA) {
        int j = idx - NWT;
        int w = j / NWA;
        int r = j % NWA;
        int e = r / KA2, i = r % KA2;
        const float* Wa = w ? Wa2 : Wa1;
        float v = 0.f;
        if (e < ATTN_ && i < IN_DIM_) v = Wa[e*ATTN_ + i];
        g_WaTh[w*NWA + r] = __float2bfloat16_rn(v);
    } else if (idx < NWT + 2*NWA + 2*NW2) {
        int j = idx - NWT - 2*NWA;
        int w = j / NW2;
        int r = j % NW2;
        int e = r / KE_, i = r % KE_;
        const float* Wa = w ? Wa2 : Wa1;
        float v = 0.f;
        if (e < ATTN_ && i < WD_) v = Wa[e*ATTN_ + IN_DIM_ + i];
        g_Wa2h[w*NW2 + r] = __float2bfloat16_rn(v);
    }
}

// ---------------- gather: bf16, masked, padded ----------------
__global__ void k_gather(const int* __restrict__ words,
                         const int* __restrict__ d1i,
                         const int* __restrict__ d2i,
                         const float* __restrict__ wemb,
                         const float* __restrict__ d1e,
                         const float* __restrict__ d2e,
                         const float* __restrict__ mask) {
    int idx = blockIdx.x * blockDim.x + threadIdx.x;
    if (idx >= B_*ROWSP*IN_PAD) return;
    int i = idx % IN_PAD;
    int r = (idx / IN_PAD) % ROWSP;
    int b = idx / (IN_PAD*ROWSP);
    float v = 0.f;
    if (r >= 1 && r <= T_ && i < IN_DIM_) {
        int m = b*T_ + (r-1);
        float x;
        if (i < WD_)            x = wemb[words[m]*WD_ + i];
        else if (i < WD_+DD_)   x = d1e[d1i[m]*DD_ + (i - WD_)];
        else                    x = d2e[d2i[m]*DD_ + (i - WD_ - DD_)];
        v = x * mask[m];
    }
    g_inpb[idx] = __float2bfloat16_rn(v);
}

// ---------------- arg embeddings -> bf16 padded [w][b][320] ----------------
__global__ void k_argemb(const int* __restrict__ arg1,
                         const int* __restrict__ arg2,
                         const float* __restrict__ wemb) {
    int idx = blockIdx.x * blockDim.x + threadIdx.x;
    if (idx >= 2*B_*KE_) return;
    int i = idx % KE_;
    int b = (idx / KE_) % B_;
    int w = idx / (B_*KE_);
    const int* arg = w ? arg2 : arg1;
    float v = (i < WD_) ? wemb[arg[b]*WD_ + i] : 0.f;
    g_argb[idx] = __float2bfloat16_rn(v);
}

// ---------------- unified bf16 GEMM: conv / attn / c-gemm ----------------
__global__ __launch_bounds__(256, 2) void k_gemm(const float* __restrict__ wr1,
                                                 const float* __restrict__ wr2,
                                                 int base) {
    extern __shared__ float smem[];
    __shared__ float cs[128], wrs[128];
    uint32_t sb = (uint32_t)__cvta_generic_to_shared(smem);

    int bid = blockIdx.x + base;
    int tid = threadIdx.x;
    int lane = tid & 31, warp = tid >> 5;
    int warpM = warp & 1, warpN = warp >> 1;
    int g = lane >> 2, t = lane & 3;

    float acc[4][4][4];
    #pragma unroll
    for (int mi = 0; mi < 4; ++mi)
        #pragma unroll
        for (int ni = 0; ni < 4; ++ni)
            #pragma unroll
            for (int c = 0; c < 4; ++c) acc[mi][ni][c] = 0.f;

    uint32_t abuf[NSTG], bbuf[NSTG];
    #pragma unroll
    for (int s = 0; s < NSTG; ++s) {
        abuf[s] = sb + (uint32_t)(2*s)*TILE_B;
        bbuf[s] = sb + (uint32_t)(2*s + 1)*TILE_B;
    }

    int mode;                        // 0 conv, 1 attn, 2 c-gemm
    int b = 0, n0, NT;
    const __nv_bfloat16* Bsrc;
    const __nv_bfloat16* Aexp = 0;   // mode-2 A base
    int BK;
    int w = 0, chunk = 0, mt = 0;
    if (bid < 1024) {
        mode = 0;
        n0 = (bid & 3) << 7;
        b  = bid >> 2;
        NT = NSC_C/2;                // 20
        Bsrc = g_Wth;
        BK = KC3;
    } else if (bid < 4096) {
        mode = 1;
        int id = bid - 1024;
        w = id & 1;
        chunk = (id >> 1) % 6;
        b = id / 12;
        n0 = chunk * 128;
        NT = NSC_A/2;                // 7
        Bsrc = &g_WaTh[w*NPADA*KA2];
        BK = KA2;
        const float* wr = w ? wr2 : wr1;
        const float* cb = &g_c[w][b*ATTN_];
        if (tid < 128) {
            int n = n0 + tid;
            cs[tid]  = (n < ATTN_) ? cb[n] : 0.f;
            wrs[tid] = (n < ATTN_) ? wr[n] : 0.f;
        }
    } else {
        mode = 2;
        int id = bid - 4096;         // 24 blocks: w*12 + mt*6 + chunk
        w = id / 12;
        int r = id % 12;
        mt = r / 6;
        chunk = r % 6;
        n0 = chunk * 128;
        NT = 5;                      // K=320 -> 10 subchunks
        Bsrc = &g_Wa2h[w*NPADA*KE_];
        BK = KE_;
        Aexp = &g_argb[(w*B_ + mt*128)*KE_];
    }

    int l_row = tid >> 2, l_grp = tid & 3;
    int l_row2 = (tid + 256) >> 2, l_grp2 = (tid + 256) & 3;

    auto load_stage = [&](int st, int s) {
        #pragma unroll
        for (int sub = 0; sub < 2; ++sub) {
            int sc = 2*st + sub;
            const __nv_bfloat16* aptr;
            int astride;
            if (mode == 0) {
                int h, i0;
                if (sc < 39) { h = sc / 13; i0 = (sc - h*13) * 32; }
                else         { h = 0; i0 = 0; }
                aptr = &g_inpb[(b*ROWSP + h)*IN_PAD + i0];
                astride = IN_PAD;
            } else if (mode == 1) {
                int i0 = (sc < 13) ? sc*32 : 0;
                aptr = &g_inpb[(b*ROWSP + 1)*IN_PAD + i0];
                astride = IN_PAD;
            } else {
                aptr = Aexp + sc*32;
                astride = KE_;
            }
            int k0 = sc * 32;
            uint32_t colb = (uint32_t)(sub * 64);
            cpa16(abuf[s] + (uint32_t)(l_row*LDAB) + colb + (uint32_t)(l_grp*16),
                  aptr + l_row*astride + l_grp*8);
            cpa16(bbuf[s] + (uint32_t)(l_row*LDAB) + colb + (uint32_t)(l_grp*16),
                  &Bsrc[(n0 + l_row)*BK + k0 + l_grp*8]);
            cpa16(abuf[s] + (uint32_t)(l_row2*LDAB) + colb + (uint32_t)(l_grp2*16),
                  aptr + l_row2*astride + l_grp2*8);
            cpa16(bbuf[s] + (uint32_t)(l_row2*LDAB) + colb + (uint32_t)(l_grp2*16),
                  &Bsrc[(n0 + l_row2)*BK + k0 + l_grp2*8]);
        }
        CP_COMMIT();
    };

    uint32_t a_off[4], b_off[2];
    #pragma unroll
    for (int mi = 0; mi < 4; ++mi) {
        int row = warpM*64 + mi*16 + (lane & 15);
        a_off[mi] = (uint32_t)(row*LDAB + ((lane >> 4) << 4));
    }
    #pragma unroll
    for (int nip = 0; nip < 2; ++nip) {
        int row = warpN*32 + nip*16 + (lane & 7) + ((lane >> 4) << 3);
        b_off[nip] = (uint32_t)(row*LDAB + (((lane >> 3) & 1) << 4));
    }

    load_stage(0, 0);
    load_stage(1, 1);

    int s = 0;
    for (int st = 0; st < NT; ++st) {
        CP_WAIT(1);
        __syncthreads();
        if (st + 2 < NT) {
            int s2 = s + 2; if (s2 >= NSTG) s2 -= NSTG;
            load_stage(st + 2, s2);
        } else {
            CP_COMMIT();
        }
        #pragma unroll
        for (int ks = 0; ks < 4; ++ks) {
            uint32_t af[4][4], bf[4][2];
            #pragma unroll
            for (int mi = 0; mi < 4; ++mi)
                ldsm4(af[mi], abuf[s] + a_off[mi] + ks*32);
            #pragma unroll
            for (int nip = 0; nip < 2; ++nip)
                ldsm4(&bf[2*nip][0], bbuf[s] + b_off[nip] + ks*32);
            #pragma unroll
            for (int mi = 0; mi < 4; ++mi)
                #pragma unroll
                for (int ni = 0; ni < 4; ++ni)
                    MMA_BF16(acc[mi][ni], af[mi], bf[ni]);
        }
        if (++s >= NSTG) s = 0;
    }
    __syncthreads();

    if (mode == 0) {
        float cm[4][2];
        #pragma unroll
        for (int ni = 0; ni < 4; ++ni) { cm[ni][0] = -1e30f; cm[ni][1] = -1e30f; }
        #pragma unroll
        for (int mi = 0; mi < 4; ++mi)
            #pragma unroll
            for (int ni = 0; ni < 4; ++ni) {
                cm[ni][0] = fmaxf(cm[ni][0], fmaxf(acc[mi][ni][0], acc[mi][ni][2]));
                cm[ni][1] = fmaxf(cm[ni][1], fmaxf(acc[mi][ni][1], acc[mi][ni][3]));
            }
        #pragma unroll
        for (int off = 4; off < 32; off <<= 1)
            #pragma unroll
            for (int ni = 0; ni < 4; ++ni) {
                cm[ni][0] = fmaxf(cm[ni][0], __shfl_xor_sync(0xffffffffu, cm[ni][0], off));
                cm[ni][1] = fmaxf(cm[ni][1], __shfl_xor_sync(0xffffffffu, cm[ni][1], off));
            }
        float* smax = smem;
        if (g == 0) {
            #pragma unroll
            for (int ni = 0; ni < 4; ++ni) {
                int col = warpN*32 + ni*8 + 2*t;
                smax[warpM*128 + col]     = cm[ni][0];
                smax[warpM*128 + col + 1] = cm[ni][1];
            }
        }
        __syncthreads();
        if (tid < 128)
            g_cnnmax[b*NF_ + n0 + tid] = fmaxf(smax[tid], smax[128 + tid]);
    } else if (mode == 1) {
        float rowacc[4][2];
        #pragma unroll
        for (int mi = 0; mi < 4; ++mi) {
            #pragma unroll
            for (int rr = 0; rr < 2; ++rr) {
                float rp = 0.f;
                #pragma unroll
                for (int ni = 0; ni < 4; ++ni)
                    #pragma unroll
                    for (int c = 0; c < 2; ++c) {
                        int col = warpN*32 + ni*8 + 2*t + c;
                        rp += wrs[col] * tanhf(acc[mi][ni][rr*2 + c] + cs[col]);
                    }
                rowacc[mi][rr] = rp;
            }
        }
        #pragma unroll
        for (int off = 1; off < 4; off <<= 1)
            #pragma unroll
            for (int mi = 0; mi < 4; ++mi)
                #pragma unroll
                for (int rr = 0; rr < 2; ++rr)
                    rowacc[mi][rr] += __shfl_xor_sync(0xffffffffu, rowacc[mi][rr], off);
        float* red = smem;
        if (t == 0) {
            #pragma unroll
            for (int mi = 0; mi < 4; ++mi)
                #pragma unroll
                for (int rr = 0; rr < 2; ++rr) {
                    int row = warpM*64 + mi*16 + g + rr*8;
                    red[warpN*128 + row] = rowacc[mi][rr];
                }
        }
        __syncthreads();
        if (tid < 128) {
            float sv = red[tid] + red[128 + tid] + red[256 + tid] + red[384 + tid];
            g_spart[(w*6 + chunk)*M_ + b*T_ + tid] = sv;
        }
    } else {
        // c-gemm: store accumulators directly to g_c
        #pragma unroll
        for (int mi = 0; mi < 4; ++mi)
            #pragma unroll
            for (int rr = 0; rr < 2; ++rr) {
                int bb = mt*128 + warpM*64 + mi*16 + g + rr*8;
                #pragma unroll
                for (int ni = 0; ni < 4; ++ni)
                    #pragma unroll
                    for (int c = 0; c < 2; ++c) {
                        int col = n0 + warpN*32 + ni*8 + 2*t + c;
                        if (col < ATTN_)
                            g_c[w][bb*ATTN_ + col] = acc[mi][ni][rr*2 + c];
                    }
            }
    }
}

// ---------------- fused softmax + wsum + final dense + softmax ----------------
__global__ __launch_bounds__(512) void k_post(const float* __restrict__ mask,
                                              const float* __restrict__ conv_b,
                                              const float* __restrict__ dw,
                                              const float* __restrict__ db,
                                              float* __restrict__ out) {
    int b = blockIdx.x;
    int tid = threadIdx.x;
    __shared__ float aw[2][128];
    __shared__ float sh[2][128];
    __shared__ float feat[FEAT_];
    __shared__ float lg[NCLS_];
    int w = (tid >> 7) & 1, t = tid & 127;

    float s = 0.f, e = 0.f;
    if (tid < 256) {
        #pragma unroll
        for (int c = 0; c < 6; ++c) s += g_spart[(w*6 + c)*M_ + b*T_ + t];
        if (mask[b*T_ + t] == 0.f) s = -1e30f;
        sh[w][t] = s;
    }
    __syncthreads();
    for (int o = 64; o > 0; o >>= 1) {
        if (tid < 256 && t < o) sh[w][t] = fmaxf(sh[w][t], sh[w][t + o]);
        __syncthreads();
    }
    float mx = (tid < 256) ? sh[w][0] : 0.f;
    __syncthreads();
    if (tid < 256) { e = expf(s - mx); sh[w][t] = e; }
    __syncthreads();
    for (int o = 64; o > 0; o >>= 1) {
        if (tid < 256 && t < o) sh[w][t] += sh[w][t + o];
        __syncthreads();
    }
    if (tid < 256) aw[w][t] = e / sh[w][0];
    __syncthreads();

    for (int idx = tid; idx < 2*IN_DIM_; idx += 512) {
        int w2 = idx / IN_DIM_, d = idx % IN_DIM_;
        float s2 = 0.f;
        #pragma unroll 4
        for (int t2 = 0; t2 < T_; ++t2)
            s2 += aw[w2][t2] * __bfloat162float(g_inpb[(b*ROWSP + t2 + 1)*IN_PAD + d]);
        feat[NF_ + idx] = s2;
    }
    feat[tid] = tanhf(g_cnnmax[b*NF_ + tid] + conv_b[tid]);
    __syncthreads();

    int warp = tid >> 5, lane = tid & 31;
    for (int c = warp; c < NCLS_; c += 16) {
        float s3 = 0.f;
        for (int i = lane; i < FEAT_; i += 32) s3 += feat[i] * dw[c*FEAT_ + i];
        #pragma unroll
        for (int off = 16; off > 0; off >>= 1)
            s3 += __shfl_xor_sync(0xffffffffu, s3, off);
        if (lane == 0) lg[c] = s3 + db[c];
    }
    __syncthreads();
    if (tid == 0) {
        float mx2 = lg[0];
        #pragma unroll
        for (int c = 1; c < NCLS_; ++c) mx2 = fmaxf(mx2, lg[c]);
        float sm = 0.f, ee[NCLS_];
        #pragma unroll
        for (int c = 0; c < NCLS_; ++c) { ee[c] = expf(lg[c] - mx2); sm += ee[c]; }
        #pragma unroll
        for (int c = 0; c < NCLS_; ++c) out[b*NCLS_ + c] = ee[c] / sm;
    }
}

// ---------------- launch ----------------
extern "C" void kernel_launch(void* const* d_in, const int* in_sizes, int n_in,
                              void* d_out, int out_size) {
    const int*   words  = (const int*)d_in[0];
    const float* mask   = (const float*)d_in[1];
    const int*   d1i    = (const int*)d_in[2];
    const int*   d2i    = (const int*)d_in[3];
    const int*   arg1   = (const int*)d_in[7];
    const int*   arg2   = (const int*)d_in[8];
    const float* wemb   = (const float*)d_in[9];
    const float* d1e    = (const float*)d_in[10];
    const float* d2e    = (const float*)d_in[11];
    const float* Wa1    = (const float*)d_in[12];
    const float* wr1    = (const float*)d_in[13];
    const float* Wa2    = (const float*)d_in[14];
    const float* wr2    = (const float*)d_in[15];
    const float* conv_w = (const float*)d_in[16];
    const float* conv_b = (const float*)d_in[17];
    const float* dw     = (const float*)d_in[18];
    const float* db     = (const float*)d_in[19];
    float* out = (float*)d_out;

    cudaFuncSetAttribute(k_gemm, cudaFuncAttributeMaxDynamicSharedMemorySize, SMEM_BYTES);

    const int NPREP = NF_*KC3 + 2*NPADA*KA2 + 2*NPADA*KE_;
    k_prep<<<(NPREP + 255)/256, 256>>>(conv_w, Wa1, Wa2);
    k_gather<<<(B_*ROWSP*IN_PAD + 255)/256, 256>>>(words, d1i, d2i, wemb, d1e, d2e, mask);
    k_argemb<<<(2*B_*KE_ + 255)/256, 256>>>(arg1, arg2, wemb);
    k_gemm<<<24, 256, SMEM_BYTES>>>(wr1, wr2, 4096);     // c-gemm first
    k_gemm<<<4096, 256, SMEM_BYTES>>>(wr1, wr2, 0);      // conv + attn
    k_post<<<B_, 512>>>(mask, conv_b, dw, db, out);
}